// round 3
// baseline (speedup 1.0000x reference)
#include <cuda_runtime.h>
#include <cstdint>

typedef unsigned long long ull;

// Problem constants (fixed by the reference).
#define NP    16384
#define FIN   64
#define MC    4096
#define KN    64
#define FH    64
#define FO    128
#define FD    67
#define FPAD  68
#define R2F   0.04f

// Scratch (static __device__ — no allocations allowed).
__device__ int   g_idx[MC];
__device__ float g_pos_s[MC * 3];
__device__ int   g_nbr[MC * KN];
__device__ int   g_cnt[MC];
// Morton-reordered cloud
__device__ float g_px[NP], g_py[NP], g_pz[NP];
__device__ int   g_orig[NP];

// ---------------------------------------------------------------------------
// 0) Build: Morton sort (bitonic, one CTA) -> reordered coords.
// ---------------------------------------------------------------------------
__device__ __forceinline__ unsigned expand10(unsigned v) {
    v &= 1023u;
    v = (v | (v << 16)) & 0x030000FFu;
    v = (v | (v << 8))  & 0x0300F00Fu;
    v = (v | (v << 4))  & 0x030C30C3u;
    v = (v | (v << 2))  & 0x09249249u;
    return v;
}

#define BLD_T 512
#define BLD_SMEM (NP * 8)

__global__ __launch_bounds__(BLD_T) void build_kernel(const float* __restrict__ pos)
{
    extern __shared__ ull sk[];
    int t = threadIdx.x;

    for (int i = t; i < NP; i += BLD_T) {
        float x = pos[3 * i + 0], y = pos[3 * i + 1], z = pos[3 * i + 2];
        unsigned ux = (unsigned)fminf(1023.f, fmaxf(0.f, (x + 5.12f) * 100.0f));
        unsigned uy = (unsigned)fminf(1023.f, fmaxf(0.f, (y + 5.12f) * 100.0f));
        unsigned uz = (unsigned)fminf(1023.f, fmaxf(0.f, (z + 5.12f) * 100.0f));
        unsigned code = (expand10(ux) << 2) | (expand10(uy) << 1) | expand10(uz);
        sk[i] = ((ull)code << 32) | (unsigned)i;
    }
    __syncthreads();

    for (unsigned k2 = 2; k2 <= NP; k2 <<= 1) {
        for (unsigned j = k2 >> 1; j > 0; j >>= 1) {
            for (unsigned i = t; i < NP; i += BLD_T) {
                unsigned ixj = i ^ j;
                if (ixj > i) {
                    ull a = sk[i], b = sk[ixj];
                    bool up = ((i & k2) == 0);
                    if ((a > b) == up) { sk[i] = b; sk[ixj] = a; }
                }
            }
            __syncthreads();
        }
    }

    for (int i = t; i < NP; i += BLD_T) {
        unsigned idx = (unsigned)sk[i];
        g_px[i] = pos[3 * idx + 0];
        g_py[i] = pos[3 * idx + 1];
        g_pz[i] = pos[3 * idx + 2];
        g_orig[i] = (int)idx;
    }
}

// ---------------------------------------------------------------------------
// 1) FPS — single persistent CTA, register-resident, per-lane AABB pruning.
//    Thread t owns the 32 Morton-contiguous points [32t, 32t+32).
//    Values bit-identical to dense FPS: skipped lanes provably unchanged.
// ---------------------------------------------------------------------------
#define FPS_T 512
#define PPT   32
#define FPS_SMEM (NP * 4 /*z*/ + NP * 4 /*orig*/ + 256)

__global__ __launch_bounds__(FPS_T) void fps_kernel(const float* __restrict__ pos)
{
    extern __shared__ unsigned char raw[];
    float*    s_z    = (float*)raw;                      // [PPT][FPS_T] transposed
    int*      s_or   = (int*)(raw + NP * 4);             // [PPT][FPS_T] transposed
    unsigned* s_wmax = (unsigned*)(raw + NP * 8);        // [16]
    unsigned* s_v    = s_wmax + 16;                      // [1]
    unsigned* s_win  = s_v + 1;                          // [2]
    float*    s_q    = (float*)(s_win + 2);              // [3]

    int t = threadIdx.x, lane = t & 31, warp = t >> 5;
    int base = t * PPT;

    float px[PPT], py[PPT], md[PPT];
    float xlo = 1e30f, xhi = -1e30f, ylo = 1e30f, yhi = -1e30f, zlo = 1e30f, zhi = -1e30f;
#pragma unroll
    for (int m = 0; m < PPT; m++) {
        float x = g_px[base + m], y = g_py[base + m], z = g_pz[base + m];
        px[m] = x; py[m] = y;
        s_z[m * FPS_T + t]  = z;
        s_or[m * FPS_T + t] = g_orig[base + m];
        xlo = fminf(xlo, x); xhi = fmaxf(xhi, x);
        ylo = fminf(ylo, y); yhi = fmaxf(yhi, y);
        zlo = fminf(zlo, z); zhi = fmaxf(zhi, z);
        md[m] = __int_as_float(0x7f800000);   // +inf
    }
    float lanebest = __int_as_float(0x7f800000);

    if (t == 0) {
        g_idx[0] = 0;
        s_q[0] = pos[0]; s_q[1] = pos[1]; s_q[2] = pos[2];
        s_win[0] = 0u; s_win[1] = 0u;
    }
    __syncthreads();

    for (int it = 1; it < MC; it++) {
        float qx = s_q[0], qy = s_q[1], qz = s_q[2];

        // Conservative lower bound of d2 from q to this lane's AABB.
        float ddx = fmaxf(fmaxf(xlo - qx, qx - xhi), 0.0f);
        float ddy = fmaxf(fmaxf(ylo - qy, qy - yhi), 0.0f);
        float ddz = fmaxf(fmaxf(zlo - qz, qz - zhi), 0.0f);
        float lb = (ddx * ddx + ddy * ddy + ddz * ddz) * 0.9999f;
        bool dirty = lb < lanebest;   // skip is value-preserving (margin >> fp error)

        if (__any_sync(0xFFFFFFFFu, dirty)) {
            if (dirty) {
                float best = -1.0f;
#pragma unroll
                for (int m = 0; m < PPT; m++) {
                    // Bit-exact replication of the reference's fused d2.
                    float dx = __fadd_rn(px[m], -qx);
                    float dy = __fadd_rn(py[m], -qy);
                    float dz = __fadd_rn(s_z[m * FPS_T + t], -qz);
                    float d2 = __fmaf_rn(dz, dz, __fmaf_rn(dy, dy, __fmul_rn(dx, dx)));
                    float mm = fminf(md[m], d2);
                    md[m] = mm;
                    best = fmaxf(best, mm);
                }
                lanebest = best;
            }
        }

        // Block argmax of lanebest (value only; d2>=0 -> u32 order == float order).
        unsigned wm = __reduce_max_sync(0xFFFFFFFFu, __float_as_uint(lanebest));
        if (lane == 0) s_wmax[warp] = wm;
        __syncthreads();                                    // B1
        if (warp == 0) {
            unsigned v = (lane < 16) ? s_wmax[lane] : 0u;
            v = __reduce_max_sync(0xFFFFFFFFu, v);
            if (lane == 0) s_v[0] = v;
        }
        __syncthreads();                                    // B2
        unsigned v = s_v[0];
        int slot = it & 1;

        // Exact tie rule: all points with md == v* compete, lowest orig wins.
        if (__float_as_uint(lanebest) == v) {
#pragma unroll 1
            for (int m = 0; m < PPT; m++)
                if (__float_as_uint(md[m]) == v)
                    atomicMax(&s_win[slot], 0xFFFFFFFFu - (unsigned)s_or[m * FPS_T + t]);
        }
        __syncthreads();                                    // B3
        unsigned worig = 0xFFFFFFFFu - s_win[slot];
        if (t == 0) { g_idx[it] = (int)worig; s_win[slot ^ 1] = 0u; }
        if (__float_as_uint(lanebest) == v) {
#pragma unroll 1
            for (int m = 0; m < PPT; m++)
                if (__float_as_uint(md[m]) == v &&
                    (unsigned)s_or[m * FPS_T + t] == worig) {
                    s_q[0] = px[m]; s_q[1] = py[m]; s_q[2] = s_z[m * FPS_T + t];
                }
        }
        __syncthreads();                                    // B4
    }
}

// ---------------------------------------------------------------------------
// 2) Gather sampled positions (+ tuple tail if flattened output).
// ---------------------------------------------------------------------------
__global__ void gather_kernel(const float* __restrict__ pos, float* __restrict__ out, int out_size)
{
    int c = blockIdx.x * blockDim.x + threadIdx.x;
    if (c >= MC) return;
    int j = g_idx[c];
    float x = pos[3 * j + 0], y = pos[3 * j + 1], z = pos[3 * j + 2];
    g_pos_s[3 * c + 0] = x; g_pos_s[3 * c + 1] = y; g_pos_s[3 * c + 2] = z;
    int base = MC * FO;
    if (out_size >= base + 3 * MC) {
        out[base + 3 * c + 0] = x; out[base + 3 * c + 1] = y; out[base + 3 * c + 2] = z;
    }
    if (out_size >= base + 4 * MC) out[base + 3 * MC + c] = 0.0f;
}

// ---------------------------------------------------------------------------
// 3) Radius neighbors (unchanged, passing).
// ---------------------------------------------------------------------------
#define RB_C   16
#define RB_T   256
#define RB_CAP 192

__global__ __launch_bounds__(RB_T) void radius_kernel(const float* __restrict__ pos)
{
    __shared__ float scx[RB_C], scy[RB_C], scz[RB_C];
    __shared__ int   scnt[RB_C];
    __shared__ int   sidx[RB_C][RB_CAP];
    __shared__ float sd2[RB_C][RB_CAP];

    int t = threadIdx.x;
    int c0 = blockIdx.x * RB_C;
    if (t < RB_C) {
        scx[t] = g_pos_s[3 * (c0 + t) + 0];
        scy[t] = g_pos_s[3 * (c0 + t) + 1];
        scz[t] = g_pos_s[3 * (c0 + t) + 2];
        scnt[t] = 0;
    }
    __syncthreads();

    for (int j = t; j < NP; j += RB_T) {
        float x = pos[3 * j + 0], y = pos[3 * j + 1], z = pos[3 * j + 2];
#pragma unroll
        for (int c = 0; c < RB_C; c++) {
            float dx = __fadd_rn(scx[c], -x);
            float dy = __fadd_rn(scy[c], -y);
            float dz = __fadd_rn(scz[c], -z);
            float d2 = __fmaf_rn(dz, dz, __fmaf_rn(dy, dy, __fmul_rn(dx, dx)));
            if (d2 <= R2F) {
                int n = atomicAdd(&scnt[c], 1);
                if (n < RB_CAP) { sidx[c][n] = j; sd2[c][n] = d2; }
            }
        }
    }
    __syncthreads();

    for (int c = 0; c < RB_C; c++) {
        int cnt = min(scnt[c], RB_CAP);
        int cg = c0 + c;
        if (cnt <= KN) {
            if (t < cnt) g_nbr[cg * KN + t] = sidx[c][t];
            if (t == 0)  g_cnt[cg] = cnt;
        } else {
            for (int i = t; i < cnt; i += RB_T) {
                float di = sd2[c][i]; int ii = sidx[c][i];
                int rank = 0;
                for (int jj = 0; jj < cnt; jj++) {
                    float dj = sd2[c][jj];
                    rank += (dj < di) || (dj == di && sidx[c][jj] < ii);
                }
                if (rank < KN) g_nbr[cg * KN + rank] = ii;
            }
            if (t == 0) g_cnt[cg] = KN;
        }
    }
}

// ---------------------------------------------------------------------------
// 4) Per-edge MLP + max-pool (unchanged, passing).
// ---------------------------------------------------------------------------
#define ML_T    256
#define ML_GRID 304

#define OFF_W1 0
#define OFF_W2 (OFF_W1 + FD * FH)
#define OFF_W3 (OFF_W2 + FH * FH)
#define OFF_B1 (OFF_W3 + FH * FO)
#define OFF_B2 (OFF_B1 + FH)
#define OFF_B3 (OFF_B2 + FH)
#define OFF_F  (OFF_B3 + FO)
#define OFF_H  (OFF_F + KN * FPAD)
#define OFF_O  (OFF_H + KN * FPAD)
#define ML_SMEM ((OFF_O + FO) * 4)

__global__ __launch_bounds__(ML_T, 2) void mlp_kernel(
    const float* __restrict__ x, const float* __restrict__ pos,
    const float* __restrict__ W1, const float* __restrict__ b1,
    const float* __restrict__ W2, const float* __restrict__ b2,
    const float* __restrict__ W3, const float* __restrict__ b3,
    float* __restrict__ out)
{
    extern __shared__ float sm[];
    float* sW1 = sm + OFF_W1;
    float* sW2 = sm + OFF_W2;
    float* sW3 = sm + OFF_W3;
    float* sb1 = sm + OFF_B1;
    float* sb2 = sm + OFF_B2;
    float* sb3 = sm + OFF_B3;
    float* sF  = sm + OFF_F;
    float* sH  = sm + OFF_H;
    int*   sO  = (int*)(sm + OFF_O);

    int t = threadIdx.x;
    for (int i = t; i < FD * FH; i += ML_T) sW1[i] = W1[i];
    for (int i = t; i < FH * FH; i += ML_T) sW2[i] = W2[i];
    for (int i = t; i < FH * FO; i += ML_T) sW3[i] = W3[i];
    if (t < FH) { sb1[t] = b1[t]; sb2[t] = b2[t]; }
    if (t < FO) sb3[t] = b3[t];

    int ei = t >> 4, ci = t & 15;

    for (int c = blockIdx.x; c < MC; c += gridDim.x) {
        __syncthreads();
        if (t < FO) sO[t] = 0;
        int E = g_cnt[c];
        float cx = g_pos_s[3 * c + 0], cy = g_pos_s[3 * c + 1], cz = g_pos_s[3 * c + 2];

        {
            int e = t >> 2, q = t & 3;
            if (e < E) {
                int nb = g_nbr[c * KN + e];
                const float4* xr = (const float4*)(x + (size_t)nb * FIN);
                float4* dst = (float4*)(sF + e * FPAD + q * 16);
                dst[0] = xr[q * 4 + 0]; dst[1] = xr[q * 4 + 1];
                dst[2] = xr[q * 4 + 2]; dst[3] = xr[q * 4 + 3];
                if (q == 0) {
                    sF[e * FPAD + 64] = pos[3 * nb + 0] - cx;
                    sF[e * FPAD + 65] = pos[3 * nb + 1] - cy;
                    sF[e * FPAD + 66] = pos[3 * nb + 2] - cz;
                    sF[e * FPAD + 67] = 0.0f;
                }
            }
        }
        __syncthreads();
        int ET = (E + 3) >> 2;

        if (ei < ET) {
            float acc[4][4];
#pragma unroll
            for (int j = 0; j < 4; j++)
#pragma unroll
                for (int a = 0; a < 4; a++) acc[j][a] = sb1[ci * 4 + a];
#pragma unroll 4
            for (int k = 0; k < FD; k++) {
                float4 wv = *(const float4*)(sW1 + k * FH + ci * 4);
                float f[4];
#pragma unroll
                for (int j = 0; j < 4; j++) f[j] = sF[(4 * ei + j) * FPAD + k];
#pragma unroll
                for (int j = 0; j < 4; j++) {
                    acc[j][0] += f[j] * wv.x; acc[j][1] += f[j] * wv.y;
                    acc[j][2] += f[j] * wv.z; acc[j][3] += f[j] * wv.w;
                }
            }
#pragma unroll
            for (int j = 0; j < 4; j++)
#pragma unroll
                for (int a = 0; a < 4; a++)
                    sH[(4 * ei + j) * FPAD + ci * 4 + a] = fmaxf(acc[j][a], 0.0f);
        }
        __syncthreads();

        if (ei < ET) {
            float acc[4][4];
#pragma unroll
            for (int j = 0; j < 4; j++)
#pragma unroll
                for (int a = 0; a < 4; a++) acc[j][a] = sb2[ci * 4 + a];
#pragma unroll 4
            for (int k = 0; k < FH; k++) {
                float4 wv = *(const float4*)(sW2 + k * FH + ci * 4);
                float f[4];
#pragma unroll
                for (int j = 0; j < 4; j++) f[j] = sH[(4 * ei + j) * FPAD + k];
#pragma unroll
                for (int j = 0; j < 4; j++) {
                    acc[j][0] += f[j] * wv.x; acc[j][1] += f[j] * wv.y;
                    acc[j][2] += f[j] * wv.z; acc[j][3] += f[j] * wv.w;
                }
            }
#pragma unroll
            for (int j = 0; j < 4; j++)
#pragma unroll
                for (int a = 0; a < 4; a++)
                    sF[(4 * ei + j) * FPAD + ci * 4 + a] = fmaxf(acc[j][a], 0.0f);
        }
        __syncthreads();

        if (ei < ET) {
            float acc[4][8];
#pragma unroll
            for (int j = 0; j < 4; j++)
#pragma unroll
                for (int a = 0; a < 8; a++) acc[j][a] = sb3[ci * 8 + a];
#pragma unroll 4
            for (int k = 0; k < FH; k++) {
                float4 wa = *(const float4*)(sW3 + k * FO + ci * 8);
                float4 wb = *(const float4*)(sW3 + k * FO + ci * 8 + 4);
                float f[4];
#pragma unroll
                for (int j = 0; j < 4; j++) f[j] = sF[(4 * ei + j) * FPAD + k];
#pragma unroll
                for (int j = 0; j < 4; j++) {
                    acc[j][0] += f[j] * wa.x; acc[j][1] += f[j] * wa.y;
                    acc[j][2] += f[j] * wa.z; acc[j][3] += f[j] * wa.w;
                    acc[j][4] += f[j] * wb.x; acc[j][5] += f[j] * wb.y;
                    acc[j][6] += f[j] * wb.z; acc[j][7] += f[j] * wb.w;
                }
            }
#pragma unroll
            for (int a = 0; a < 8; a++) {
                float mv = -1.0f;
#pragma unroll
                for (int j = 0; j < 4; j++)
                    if (4 * ei + j < E) mv = fmaxf(mv, fmaxf(acc[j][a], 0.0f));
                if (mv >= 0.0f) atomicMax(&sO[ci * 8 + a], __float_as_int(mv));
            }
        }
        __syncthreads();
        if (t < FO) out[(size_t)c * FO + t] = __int_as_float(sO[t]);
    }
}

// ---------------------------------------------------------------------------
extern "C" void kernel_launch(void* const* d_in, const int* in_sizes, int n_in,
                              void* d_out, int out_size)
{
    const float* x   = (const float*)d_in[0];
    const float* pos = (const float*)d_in[1];
    const float* W1 = (const float*)d_in[3];
    const float* b1 = (const float*)d_in[4];
    const float* W2 = (const float*)d_in[5];
    const float* b2 = (const float*)d_in[6];
    const float* W3 = (const float*)d_in[7];
    const float* b3 = (const float*)d_in[8];
    float* out = (float*)d_out;

    cudaFuncSetAttribute(build_kernel, cudaFuncAttributeMaxDynamicSharedMemorySize, BLD_SMEM);
    cudaFuncSetAttribute(fps_kernel,   cudaFuncAttributeMaxDynamicSharedMemorySize, FPS_SMEM);
    cudaFuncSetAttribute(mlp_kernel,   cudaFuncAttributeMaxDynamicSharedMemorySize, ML_SMEM);

    build_kernel<<<1, BLD_T, BLD_SMEM>>>(pos);
    fps_kernel<<<1, FPS_T, FPS_SMEM>>>(pos);
    gather_kernel<<<(MC + 255) / 256, 256>>>(pos, out, out_size);
    radius_kernel<<<MC / RB_C, RB_T>>>(pos);
    mlp_kernel<<<ML_GRID, ML_T, ML_SMEM>>>(x, pos, W1, b1, W2, b2, W3, b3, out);
}

// round 4
// speedup vs baseline: 5.4648x; 5.4648x over previous
#include <cuda_runtime.h>
#include <cstdint>

typedef unsigned long long ull;

// Problem constants (fixed by the reference).
#define NP    16384
#define FIN   64
#define MC    4096
#define KN    64
#define FH    64
#define FO    128
#define FD    67
#define FPAD  68
#define R2F   0.04f

// Scratch (static __device__ — no allocations allowed).
__device__ int   g_idx[MC];
__device__ float g_pos_s[MC * 3];
__device__ int   g_nbr[MC * KN];
__device__ int   g_cnt[MC];
// Morton-reordered cloud
__device__ float g_px[NP], g_py[NP], g_pz[NP];
__device__ int   g_orig[NP];

// ---------------------------------------------------------------------------
// 0) Build: Morton sort (bitonic, one CTA) -> reordered coords.
// ---------------------------------------------------------------------------
__device__ __forceinline__ unsigned expand10(unsigned v) {
    v &= 1023u;
    v = (v | (v << 16)) & 0x030000FFu;
    v = (v | (v << 8))  & 0x0300F00Fu;
    v = (v | (v << 4))  & 0x030C30C3u;
    v = (v | (v << 2))  & 0x09249249u;
    return v;
}

#define BLD_T 512
#define BLD_SMEM (NP * 8)

__global__ __launch_bounds__(BLD_T) void build_kernel(const float* __restrict__ pos)
{
    extern __shared__ ull sk[];
    int t = threadIdx.x;

    for (int i = t; i < NP; i += BLD_T) {
        float x = pos[3 * i + 0], y = pos[3 * i + 1], z = pos[3 * i + 2];
        unsigned ux = (unsigned)fminf(1023.f, fmaxf(0.f, (x + 5.12f) * 100.0f));
        unsigned uy = (unsigned)fminf(1023.f, fmaxf(0.f, (y + 5.12f) * 100.0f));
        unsigned uz = (unsigned)fminf(1023.f, fmaxf(0.f, (z + 5.12f) * 100.0f));
        unsigned code = (expand10(ux) << 2) | (expand10(uy) << 1) | expand10(uz);
        sk[i] = ((ull)code << 32) | (unsigned)i;
    }
    __syncthreads();

    for (unsigned k2 = 2; k2 <= NP; k2 <<= 1) {
        for (unsigned j = k2 >> 1; j > 0; j >>= 1) {
            for (unsigned i = t; i < NP; i += BLD_T) {
                unsigned ixj = i ^ j;
                if (ixj > i) {
                    ull a = sk[i], b = sk[ixj];
                    bool up = ((i & k2) == 0);
                    if ((a > b) == up) { sk[i] = b; sk[ixj] = a; }
                }
            }
            __syncthreads();
        }
    }

    for (int i = t; i < NP; i += BLD_T) {
        unsigned idx = (unsigned)sk[i];
        g_px[i] = pos[3 * idx + 0];
        g_py[i] = pos[3 * idx + 1];
        g_pz[i] = pos[3 * idx + 2];
        g_orig[i] = (int)idx;
    }
}

// ---------------------------------------------------------------------------
// 1) FPS — single persistent CTA. All mutable per-point state in SMEM
//    (no register arrays -> no spills). 512 groups of 32 Morton-contiguous
//    points; per-group AABB pruning (value-preserving => bit-identical).
// ---------------------------------------------------------------------------
#define FPS_T 512
#define NG    512

#define OXY   0
#define OMD   (OXY + NP * 8)
#define OGK   (OMD + NP * 4)
#define OGQ   (OGK + NG * 8)
#define ODL   (OGQ + NG * 16)
#define OMISC (ODL + NG * 4)
#define FPS_SMEM (OMISC + 64)

__global__ __launch_bounds__(FPS_T) void fps_kernel(const float* __restrict__ pos)
{
    extern __shared__ unsigned char raw[];
    float2* s_xy  = (float2*)(raw + OXY);    // [NP]
    float*  s_md  = (float*)(raw + OMD);     // [NP]
    ull*    s_gk  = (ull*)(raw + OGK);       // [NG]  (maxmd_bits<<32 | ~orig)
    float4* s_gq  = (float4*)(raw + OGQ);    // [NG]  winner coords
    int*    s_dl  = (int*)(raw + ODL);       // [NG]  dirty list
    ull*    s_v   = (ull*)(raw + OMISC);     // [2]   global key, double-buffered
    int*    s_cnt = (int*)(raw + OMISC + 16);
    float*  s_q   = (float*)(raw + OMISC + 20);  // [3]

    int t = threadIdx.x, lane = t & 31, warp = t >> 5;

    // Init: load coords, build this thread's group AABB in scalar regs.
    float xlo = 1e30f, xhi = -1e30f, ylo = 1e30f, yhi = -1e30f, zlo = 1e30f, zhi = -1e30f;
    for (int m = 0; m < 32; m++) {
        int p = (t << 5) + m;
        float x = g_px[p], y = g_py[p], z = g_pz[p];
        s_xy[p] = make_float2(x, y);
        s_md[p] = __int_as_float(0x7f800000);
        xlo = fminf(xlo, x); xhi = fmaxf(xhi, x);
        ylo = fminf(ylo, y); yhi = fmaxf(yhi, y);
        zlo = fminf(zlo, z); zhi = fmaxf(zhi, z);
    }
    s_gk[t] = ((ull)0x7f800000u << 32);
    if (t == 0) {
        g_idx[0] = 0;
        s_q[0] = pos[0]; s_q[1] = pos[1]; s_q[2] = pos[2];
        s_v[0] = 0ull; s_v[1] = 0ull;
        *s_cnt = 0;
    }
    __syncthreads();

    for (int it = 1; it < MC; it++) {
        float qx = s_q[0], qy = s_q[1], qz = s_q[2];

        // Phase A: dirty test (group t) + warp-aggregated append.
        {
            float ddx = fmaxf(fmaxf(xlo - qx, qx - xhi), 0.0f);
            float ddy = fmaxf(fmaxf(ylo - qy, qy - yhi), 0.0f);
            float ddz = fmaxf(fmaxf(zlo - qz, qz - zhi), 0.0f);
            float lb = (ddx * ddx + ddy * ddy + ddz * ddz) * 0.9999f;
            unsigned gmax = (unsigned)(s_gk[t] >> 32);
            bool dirty = __float_as_uint(lb) < gmax;   // d2>=0: bit order == float order
            unsigned msk = __ballot_sync(0xFFFFFFFFu, dirty);
            int cnt = __popc(msk);
            int base = 0;
            int leader = __ffs(msk) - 1;
            if (cnt > 0) {
                if (lane == leader) base = atomicAdd(s_cnt, cnt);
                base = __shfl_sync(0xFFFFFFFFu, base, leader);
                if (dirty)
                    s_dl[base + __popc(msk & ((1u << lane) - 1u))] = t;
            }
        }
        __syncthreads();                                  // B1

        // Phase B: warp per dirty group — update md, group key, winner coords.
        int D = *s_cnt;
        for (int d = warp; d < D; d += (FPS_T / 32)) {
            int g = s_dl[d];
            int p = (g << 5) | lane;
            float2 xy = s_xy[p];
            float z = g_pz[p];
            float dx = __fadd_rn(xy.x, -qx);
            float dy = __fadd_rn(xy.y, -qy);
            float dz = __fadd_rn(z, -qz);
            float d2 = __fmaf_rn(dz, dz, __fmaf_rn(dy, dy, __fmul_rn(dx, dx)));
            float mn = fminf(s_md[p], d2);
            s_md[p] = mn;
            unsigned hi = __float_as_uint(mn);
            unsigned wh = __reduce_max_sync(0xFFFFFFFFu, hi);
            unsigned lo_eff = 0u, myinv = 0u;
            if (hi == wh) {
                myinv = 0xFFFFFFFFu - (unsigned)g_orig[p];
                lo_eff = myinv;
            }
            unsigned wl = __reduce_max_sync(0xFFFFFFFFu, lo_eff);
            if (hi == wh && myinv == wl)
                s_gq[g] = make_float4(xy.x, xy.y, z, 0.0f);
            if (lane == 0)
                s_gk[g] = ((ull)wh << 32) | wl;
        }
        __syncthreads();                                  // B2

        // Phase C: global argmax over group keys.
        ull key = s_gk[t];
        {
            unsigned hi = (unsigned)(key >> 32), lo = (unsigned)key;
            unsigned wh = __reduce_max_sync(0xFFFFFFFFu, hi);
            unsigned le = (hi == wh) ? lo : 0u;
            unsigned wl = __reduce_max_sync(0xFFFFFFFFu, le);
            int slot = it & 1;
            if (lane == 0) atomicMax(&s_v[slot], ((ull)wh << 32) | wl);
        }
        __syncthreads();                                  // B3

        ull v = s_v[it & 1];
        if (key == v) {                                   // unique (orig unique)
            float4 q = s_gq[t];
            s_q[0] = q.x; s_q[1] = q.y; s_q[2] = q.z;
        }
        if (t == 0) {
            g_idx[it] = (int)(0xFFFFFFFFu - (unsigned)v);
            s_v[(it & 1) ^ 1] = 0ull;
            *s_cnt = 0;
        }
        __syncthreads();                                  // B4
    }
}

// ---------------------------------------------------------------------------
// 2) Gather sampled positions (+ tuple tail if flattened output).
// ---------------------------------------------------------------------------
__global__ void gather_kernel(const float* __restrict__ pos, float* __restrict__ out, int out_size)
{
    int c = blockIdx.x * blockDim.x + threadIdx.x;
    if (c >= MC) return;
    int j = g_idx[c];
    float x = pos[3 * j + 0], y = pos[3 * j + 1], z = pos[3 * j + 2];
    g_pos_s[3 * c + 0] = x; g_pos_s[3 * c + 1] = y; g_pos_s[3 * c + 2] = z;
    int base = MC * FO;
    if (out_size >= base + 3 * MC) {
        out[base + 3 * c + 0] = x; out[base + 3 * c + 1] = y; out[base + 3 * c + 2] = z;
    }
    if (out_size >= base + 4 * MC) out[base + 3 * MC + c] = 0.0f;
}

// ---------------------------------------------------------------------------
// 3) Radius neighbors (unchanged, passing).
// ---------------------------------------------------------------------------
#define RB_C   16
#define RB_T   256
#define RB_CAP 192

__global__ __launch_bounds__(RB_T) void radius_kernel(const float* __restrict__ pos)
{
    __shared__ float scx[RB_C], scy[RB_C], scz[RB_C];
    __shared__ int   scnt[RB_C];
    __shared__ int   sidx[RB_C][RB_CAP];
    __shared__ float sd2[RB_C][RB_CAP];

    int t = threadIdx.x;
    int c0 = blockIdx.x * RB_C;
    if (t < RB_C) {
        scx[t] = g_pos_s[3 * (c0 + t) + 0];
        scy[t] = g_pos_s[3 * (c0 + t) + 1];
        scz[t] = g_pos_s[3 * (c0 + t) + 2];
        scnt[t] = 0;
    }
    __syncthreads();

    for (int j = t; j < NP; j += RB_T) {
        float x = pos[3 * j + 0], y = pos[3 * j + 1], z = pos[3 * j + 2];
#pragma unroll
        for (int c = 0; c < RB_C; c++) {
            float dx = __fadd_rn(scx[c], -x);
            float dy = __fadd_rn(scy[c], -y);
            float dz = __fadd_rn(scz[c], -z);
            float d2 = __fmaf_rn(dz, dz, __fmaf_rn(dy, dy, __fmul_rn(dx, dx)));
            if (d2 <= R2F) {
                int n = atomicAdd(&scnt[c], 1);
                if (n < RB_CAP) { sidx[c][n] = j; sd2[c][n] = d2; }
            }
        }
    }
    __syncthreads();

    for (int c = 0; c < RB_C; c++) {
        int cnt = min(scnt[c], RB_CAP);
        int cg = c0 + c;
        if (cnt <= KN) {
            if (t < cnt) g_nbr[cg * KN + t] = sidx[c][t];
            if (t == 0)  g_cnt[cg] = cnt;
        } else {
            for (int i = t; i < cnt; i += RB_T) {
                float di = sd2[c][i]; int ii = sidx[c][i];
                int rank = 0;
                for (int jj = 0; jj < cnt; jj++) {
                    float dj = sd2[c][jj];
                    rank += (dj < di) || (dj == di && sidx[c][jj] < ii);
                }
                if (rank < KN) g_nbr[cg * KN + rank] = ii;
            }
            if (t == 0) g_cnt[cg] = KN;
        }
    }
}

// ---------------------------------------------------------------------------
// 4) Per-edge MLP + max-pool (unchanged, passing).
// ---------------------------------------------------------------------------
#define ML_T    256
#define ML_GRID 304

#define OFF_W1 0
#define OFF_W2 (OFF_W1 + FD * FH)
#define OFF_W3 (OFF_W2 + FH * FH)
#define OFF_B1 (OFF_W3 + FH * FO)
#define OFF_B2 (OFF_B1 + FH)
#define OFF_B3 (OFF_B2 + FH)
#define OFF_F  (OFF_B3 + FO)
#define OFF_H  (OFF_F + KN * FPAD)
#define OFF_O  (OFF_H + KN * FPAD)
#define ML_SMEM ((OFF_O + FO) * 4)

__global__ __launch_bounds__(ML_T, 2) void mlp_kernel(
    const float* __restrict__ x, const float* __restrict__ pos,
    const float* __restrict__ W1, const float* __restrict__ b1,
    const float* __restrict__ W2, const float* __restrict__ b2,
    const float* __restrict__ W3, const float* __restrict__ b3,
    float* __restrict__ out)
{
    extern __shared__ float sm[];
    float* sW1 = sm + OFF_W1;
    float* sW2 = sm + OFF_W2;
    float* sW3 = sm + OFF_W3;
    float* sb1 = sm + OFF_B1;
    float* sb2 = sm + OFF_B2;
    float* sb3 = sm + OFF_B3;
    float* sF  = sm + OFF_F;
    float* sH  = sm + OFF_H;
    int*   sO  = (int*)(sm + OFF_O);

    int t = threadIdx.x;
    for (int i = t; i < FD * FH; i += ML_T) sW1[i] = W1[i];
    for (int i = t; i < FH * FH; i += ML_T) sW2[i] = W2[i];
    for (int i = t; i < FH * FO; i += ML_T) sW3[i] = W3[i];
    if (t < FH) { sb1[t] = b1[t]; sb2[t] = b2[t]; }
    if (t < FO) sb3[t] = b3[t];

    int ei = t >> 4, ci = t & 15;

    for (int c = blockIdx.x; c < MC; c += gridDim.x) {
        __syncthreads();
        if (t < FO) sO[t] = 0;
        int E = g_cnt[c];
        float cx = g_pos_s[3 * c + 0], cy = g_pos_s[3 * c + 1], cz = g_pos_s[3 * c + 2];

        {
            int e = t >> 2, q = t & 3;
            if (e < E) {
                int nb = g_nbr[c * KN + e];
                const float4* xr = (const float4*)(x + (size_t)nb * FIN);
                float4* dst = (float4*)(sF + e * FPAD + q * 16);
                dst[0] = xr[q * 4 + 0]; dst[1] = xr[q * 4 + 1];
                dst[2] = xr[q * 4 + 2]; dst[3] = xr[q * 4 + 3];
                if (q == 0) {
                    sF[e * FPAD + 64] = pos[3 * nb + 0] - cx;
                    sF[e * FPAD + 65] = pos[3 * nb + 1] - cy;
                    sF[e * FPAD + 66] = pos[3 * nb + 2] - cz;
                    sF[e * FPAD + 67] = 0.0f;
                }
            }
        }
        __syncthreads();
        int ET = (E + 3) >> 2;

        if (ei < ET) {
            float acc[4][4];
#pragma unroll
            for (int j = 0; j < 4; j++)
#pragma unroll
                for (int a = 0; a < 4; a++) acc[j][a] = sb1[ci * 4 + a];
#pragma unroll 4
            for (int k = 0; k < FD; k++) {
                float4 wv = *(const float4*)(sW1 + k * FH + ci * 4);
                float f[4];
#pragma unroll
                for (int j = 0; j < 4; j++) f[j] = sF[(4 * ei + j) * FPAD + k];
#pragma unroll
                for (int j = 0; j < 4; j++) {
                    acc[j][0] += f[j] * wv.x; acc[j][1] += f[j] * wv.y;
                    acc[j][2] += f[j] * wv.z; acc[j][3] += f[j] * wv.w;
                }
            }
#pragma unroll
            for (int j = 0; j < 4; j++)
#pragma unroll
                for (int a = 0; a < 4; a++)
                    sH[(4 * ei + j) * FPAD + ci * 4 + a] = fmaxf(acc[j][a], 0.0f);
        }
        __syncthreads();

        if (ei < ET) {
            float acc[4][4];
#pragma unroll
            for (int j = 0; j < 4; j++)
#pragma unroll
                for (int a = 0; a < 4; a++) acc[j][a] = sb2[ci * 4 + a];
#pragma unroll 4
            for (int k = 0; k < FH; k++) {
                float4 wv = *(const float4*)(sW2 + k * FH + ci * 4);
                float f[4];
#pragma unroll
                for (int j = 0; j < 4; j++) f[j] = sH[(4 * ei + j) * FPAD + k];
#pragma unroll
                for (int j = 0; j < 4; j++) {
                    acc[j][0] += f[j] * wv.x; acc[j][1] += f[j] * wv.y;
                    acc[j][2] += f[j] * wv.z; acc[j][3] += f[j] * wv.w;
                }
            }
#pragma unroll
            for (int j = 0; j < 4; j++)
#pragma unroll
                for (int a = 0; a < 4; a++)
                    sF[(4 * ei + j) * FPAD + ci * 4 + a] = fmaxf(acc[j][a], 0.0f);
        }
        __syncthreads();

        if (ei < ET) {
            float acc[4][8];
#pragma unroll
            for (int j = 0; j < 4; j++)
#pragma unroll
                for (int a = 0; a < 8; a++) acc[j][a] = sb3[ci * 8 + a];
#pragma unroll 4
            for (int k = 0; k < FH; k++) {
                float4 wa = *(const float4*)(sW3 + k * FO + ci * 8);
                float4 wb = *(const float4*)(sW3 + k * FO + ci * 8 + 4);
                float f[4];
#pragma unroll
                for (int j = 0; j < 4; j++) f[j] = sF[(4 * ei + j) * FPAD + k];
#pragma unroll
                for (int j = 0; j < 4; j++) {
                    acc[j][0] += f[j] * wa.x; acc[j][1] += f[j] * wa.y;
                    acc[j][2] += f[j] * wa.z; acc[j][3] += f[j] * wa.w;
                    acc[j][4] += f[j] * wb.x; acc[j][5] += f[j] * wb.y;
                    acc[j][6] += f[j] * wb.z; acc[j][7] += f[j] * wb.w;
                }
            }
#pragma unroll
            for (int a = 0; a < 8; a++) {
                float mv = -1.0f;
#pragma unroll
                for (int j = 0; j < 4; j++)
                    if (4 * ei + j < E) mv = fmaxf(mv, fmaxf(acc[j][a], 0.0f));
                if (mv >= 0.0f) atomicMax(&sO[ci * 8 + a], __float_as_int(mv));
            }
        }
        __syncthreads();
        if (t < FO) out[(size_t)c * FO + t] = __int_as_float(sO[t]);
    }
}

// ---------------------------------------------------------------------------
extern "C" void kernel_launch(void* const* d_in, const int* in_sizes, int n_in,
                              void* d_out, int out_size)
{
    const float* x   = (const float*)d_in[0];
    const float* pos = (const float*)d_in[1];
    const float* W1 = (const float*)d_in[3];
    const float* b1 = (const float*)d_in[4];
    const float* W2 = (const float*)d_in[5];
    const float* b2 = (const float*)d_in[6];
    const float* W3 = (const float*)d_in[7];
    const float* b3 = (const float*)d_in[8];
    float* out = (float*)d_out;

    cudaFuncSetAttribute(build_kernel, cudaFuncAttributeMaxDynamicSharedMemorySize, BLD_SMEM);
    cudaFuncSetAttribute(fps_kernel,   cudaFuncAttributeMaxDynamicSharedMemorySize, FPS_SMEM);
    cudaFuncSetAttribute(mlp_kernel,   cudaFuncAttributeMaxDynamicSharedMemorySize, ML_SMEM);

    build_kernel<<<1, BLD_T, BLD_SMEM>>>(pos);
    fps_kernel<<<1, FPS_T, FPS_SMEM>>>(pos);
    gather_kernel<<<(MC + 255) / 256, 256>>>(pos, out, out_size);
    radius_kernel<<<MC / RB_C, RB_T>>>(pos);
    mlp_kernel<<<ML_GRID, ML_T, ML_SMEM>>>(x, pos, W1, b1, W2, b2, W3, b3, out);
}

// round 6
// speedup vs baseline: 5.6751x; 1.0385x over previous
#include <cuda_runtime.h>
#include <cstdint>

typedef unsigned long long ull;

// Problem constants (fixed by the reference).
#define NP    16384
#define FIN   64
#define MC    4096
#define KN    64
#define FH    64
#define FO    128
#define FD    67
#define FPAD  68
#define R2F   0.04f

// Scratch (static __device__ — no allocations allowed).
__device__ int   g_idx[MC];
__device__ float g_pos_s[MC * 3];
__device__ int   g_nbr[MC * KN];
__device__ int   g_cnt[MC];
// Morton-reordered cloud (128B-aligned so one group = one cache line)
__device__ __align__(128) float g_px[NP];
__device__ __align__(128) float g_py[NP];
__device__ __align__(128) float g_pz[NP];
__device__ __align__(128) int   g_orig[NP];

// ---------------------------------------------------------------------------
// 0) Build: Morton sort (bitonic, one CTA) -> reordered coords.
// ---------------------------------------------------------------------------
__device__ __forceinline__ unsigned expand10(unsigned v) {
    v &= 1023u;
    v = (v | (v << 16)) & 0x030000FFu;
    v = (v | (v << 8))  & 0x0300F00Fu;
    v = (v | (v << 4))  & 0x030C30C3u;
    v = (v | (v << 2))  & 0x09249249u;
    return v;
}

#define BLD_T 512
#define BLD_SMEM (NP * 8)

__global__ __launch_bounds__(BLD_T) void build_kernel(const float* __restrict__ pos)
{
    extern __shared__ ull sk[];
    int t = threadIdx.x;

    for (int i = t; i < NP; i += BLD_T) {
        float x = pos[3 * i + 0], y = pos[3 * i + 1], z = pos[3 * i + 2];
        unsigned ux = (unsigned)fminf(1023.f, fmaxf(0.f, (x + 5.12f) * 100.0f));
        unsigned uy = (unsigned)fminf(1023.f, fmaxf(0.f, (y + 5.12f) * 100.0f));
        unsigned uz = (unsigned)fminf(1023.f, fmaxf(0.f, (z + 5.12f) * 100.0f));
        unsigned code = (expand10(ux) << 2) | (expand10(uy) << 1) | expand10(uz);
        sk[i] = ((ull)code << 32) | (unsigned)i;
    }
    __syncthreads();

    for (unsigned k2 = 2; k2 <= NP; k2 <<= 1) {
        for (unsigned j = k2 >> 1; j > 0; j >>= 1) {
            for (unsigned i = t; i < NP; i += BLD_T) {
                unsigned ixj = i ^ j;
                if (ixj > i) {
                    ull a = sk[i], b = sk[ixj];
                    bool up = ((i & k2) == 0);
                    if ((a > b) == up) { sk[i] = b; sk[ixj] = a; }
                }
            }
            __syncthreads();
        }
    }

    for (int i = t; i < NP; i += BLD_T) {
        unsigned idx = (unsigned)sk[i];
        g_px[i] = pos[3 * idx + 0];
        g_py[i] = pos[3 * idx + 1];
        g_pz[i] = pos[3 * idx + 2];
        g_orig[i] = (int)idx;
    }
}

// ---------------------------------------------------------------------------
// 1) FPS — single persistent CTA, 256 threads / 8 warps.
//    512 groups of 32 Morton-contiguous points. Warp w owns groups
//    g == w (mod 8) (strided -> spatial dirty clusters balance across warps).
//    Thread (w, lane) owns groups g0 = w + 8*lane, g1 = g0 + 256 and keeps
//    their AABB + current group-max(min_d2) in scalar registers.
//    3 __syncthreads per iteration; no contended atomics on the hot path.
//    Pruned groups are provably unchanged -> bit-identical to dense FPS.
// ---------------------------------------------------------------------------
#define FPS_T 256
#define NG    512

#define OXY   0
#define OMD   (OXY + NP * 8)
#define OGQ   (OMD + NP * 4)
#define OWM   (OGQ + NG * 16)
#define OWIN  (OWM + 8 * 4)
#define OQ    (OWIN + 2 * 4)
#define FPS_SMEM (OQ + 16)

__global__ __launch_bounds__(FPS_T) void fps_kernel(const float* __restrict__ pos)
{
    extern __shared__ unsigned char raw[];
    float2*   s_xy  = (float2*)(raw + OXY);     // [NP]
    float*    s_md  = (float*)(raw + OMD);      // [NP]
    float4*   s_gq  = (float4*)(raw + OGQ);     // [NG] winner x,y,z,(~orig bits)
    unsigned* s_wm  = (unsigned*)(raw + OWM);   // [8]
    unsigned* s_win = (unsigned*)(raw + OWIN);  // [2]
    float*    s_q   = (float*)(raw + OQ);       // [3]

    int t = threadIdx.x, lane = t & 31, w = t >> 5;
    int g0 = w + 8 * lane;            // owned group 0
    int g1 = g0 + 256;                // owned group 1

    // Init coords + md
    for (int p = t; p < NP; p += FPS_T) {
        s_xy[p] = make_float2(g_px[p], g_py[p]);
        s_md[p] = __int_as_float(0x7f800000);
    }
    // Per-owned-group AABB in scalar registers.
    float x0lo = 1e30f, x0hi = -1e30f, y0lo = 1e30f, y0hi = -1e30f, z0lo = 1e30f, z0hi = -1e30f;
    float x1lo = 1e30f, x1hi = -1e30f, y1lo = 1e30f, y1hi = -1e30f, z1lo = 1e30f, z1hi = -1e30f;
    for (int m = 0; m < 32; m++) {
        int p = (g0 << 5) + m;
        float x = g_px[p], y = g_py[p], z = g_pz[p];
        x0lo = fminf(x0lo, x); x0hi = fmaxf(x0hi, x);
        y0lo = fminf(y0lo, y); y0hi = fmaxf(y0hi, y);
        z0lo = fminf(z0lo, z); z0hi = fmaxf(z0hi, z);
        p = (g1 << 5) + m;
        x = g_px[p]; y = g_py[p]; z = g_pz[p];
        x1lo = fminf(x1lo, x); x1hi = fmaxf(x1hi, x);
        y1lo = fminf(y1lo, y); y1hi = fmaxf(y1hi, y);
        z1lo = fminf(z1lo, z); z1hi = fmaxf(z1hi, z);
    }
    unsigned gmax0 = 0x7f800000u, gmax1 = 0x7f800000u;   // group max(md) bits

    if (t == 0) {
        g_idx[0] = 0;
        s_q[0] = pos[0]; s_q[1] = pos[1]; s_q[2] = pos[2];
        s_win[0] = 0u; s_win[1] = 0u;
    }
    __syncthreads();

    for (int it = 1; it < MC; it++) {
        float qx = s_q[0], qy = s_q[1], qz = s_q[2];

        // ---- Phase A: per-owned-group dirty test (registers only) ----
        float ddx = fmaxf(fmaxf(x0lo - qx, qx - x0hi), 0.0f);
        float ddy = fmaxf(fmaxf(y0lo - qy, qy - y0hi), 0.0f);
        float ddz = fmaxf(fmaxf(z0lo - qz, qz - z0hi), 0.0f);
        float lb0 = (ddx * ddx + ddy * ddy + ddz * ddz) * 0.9999f;
        bool d0 = lb0 < __uint_as_float(gmax0);
        ddx = fmaxf(fmaxf(x1lo - qx, qx - x1hi), 0.0f);
        ddy = fmaxf(fmaxf(y1lo - qy, qy - y1hi), 0.0f);
        ddz = fmaxf(fmaxf(z1lo - qz, qz - z1hi), 0.0f);
        float lb1 = (ddx * ddx + ddy * ddy + ddz * ddz) * 0.9999f;
        bool d1 = lb1 < __uint_as_float(gmax1);
        if (d0) {
            asm volatile("prefetch.global.L1 [%0];" :: "l"(&g_pz[g0 << 5]));
            asm volatile("prefetch.global.L1 [%0];" :: "l"(&g_orig[g0 << 5]));
        }
        if (d1) {
            asm volatile("prefetch.global.L1 [%0];" :: "l"(&g_pz[g1 << 5]));
            asm volatile("prefetch.global.L1 [%0];" :: "l"(&g_orig[g1 << 5]));
        }
        unsigned m0 = __ballot_sync(0xFFFFFFFFu, d0);
        unsigned m1 = __ballot_sync(0xFFFFFFFFu, d1);

        // ---- Phase B: warp processes its dirty groups (warp-local) ----
#pragma unroll
        for (int k = 0; k < 2; k++) {
            unsigned mk = k ? m1 : m0;
            while (mk) {
                int b = __ffs(mk) - 1;
                mk &= mk - 1;
                int g = w + 8 * (b + 32 * k);
                int p = (g << 5) | lane;
                float2 xy = s_xy[p];
                float z = g_pz[p];
                unsigned inv = ~(unsigned)g_orig[p];
                float dx = __fadd_rn(xy.x, -qx);
                float dy = __fadd_rn(xy.y, -qy);
                float dz = __fadd_rn(z, -qz);
                float d2 = __fmaf_rn(dz, dz, __fmaf_rn(dy, dy, __fmul_rn(dx, dx)));
                float mn = fminf(s_md[p], d2);
                s_md[p] = mn;
                unsigned mb = __float_as_uint(mn);
                unsigned gm = __reduce_max_sync(0xFFFFFFFFu, mb);
                unsigned tiem = __ballot_sync(0xFFFFFFFFu, mb == gm);
                if (__popc(tiem) > 1) {
                    unsigned iv = (mb == gm) ? inv : 0u;
                    unsigned wi = __reduce_max_sync(0xFFFFFFFFu, iv);
                    if (mb == gm && inv == wi)
                        s_gq[g] = make_float4(xy.x, xy.y, z, __uint_as_float(inv));
                } else if (mb == gm) {
                    s_gq[g] = make_float4(xy.x, xy.y, z, __uint_as_float(inv));
                }
                if (lane == b) {          // owner lane caches new group max
                    if (k == 0) gmax0 = gm; else gmax1 = gm;
                }
            }
        }

        // ---- Reduce: per-warp max over owned groups (registers) ----
        unsigned wmx = __reduce_max_sync(0xFFFFFFFFu, gmax0 > gmax1 ? gmax0 : gmax1);
        if (lane == 0) s_wm[w] = wmx;
        __syncthreads();                                     // BAR1

        unsigned v = __reduce_max_sync(0xFFFFFFFFu, s_wm[lane & 7]);
        int slot = it & 1;
        // Candidates (usually exactly one group): exact lowest-orig tie rule.
        if (gmax0 == v) atomicMax(&s_win[slot], __float_as_uint(s_gq[g0].w));
        if (gmax1 == v) atomicMax(&s_win[slot], __float_as_uint(s_gq[g1].w));
        __syncthreads();                                     // BAR2

        unsigned win = s_win[slot];
        if (gmax0 == v && __float_as_uint(s_gq[g0].w) == win) {
            float4 q = s_gq[g0];
            s_q[0] = q.x; s_q[1] = q.y; s_q[2] = q.z;
            g_idx[it] = (int)~win;
        }
        if (gmax1 == v && __float_as_uint(s_gq[g1].w) == win) {
            float4 q = s_gq[g1];
            s_q[0] = q.x; s_q[1] = q.y; s_q[2] = q.z;
            g_idx[it] = (int)~win;
        }
        if (t == 0) s_win[slot ^ 1] = 0u;
        __syncthreads();                                     // BAR3
    }
}

// ---------------------------------------------------------------------------
// 2) Gather sampled positions (+ tuple tail if flattened output).
// ---------------------------------------------------------------------------
__global__ void gather_kernel(const float* __restrict__ pos, float* __restrict__ out, int out_size)
{
    int c = blockIdx.x * blockDim.x + threadIdx.x;
    if (c >= MC) return;
    int j = g_idx[c];
    float x = pos[3 * j + 0], y = pos[3 * j + 1], z = pos[3 * j + 2];
    g_pos_s[3 * c + 0] = x; g_pos_s[3 * c + 1] = y; g_pos_s[3 * c + 2] = z;
    int base = MC * FO;
    if (out_size >= base + 3 * MC) {
        out[base + 3 * c + 0] = x; out[base + 3 * c + 1] = y; out[base + 3 * c + 2] = z;
    }
    if (out_size >= base + 4 * MC) out[base + 3 * MC + c] = 0.0f;
}

// ---------------------------------------------------------------------------
// 3) Radius neighbors (unchanged, passing).
// ---------------------------------------------------------------------------
#define RB_C   16
#define RB_T   256
#define RB_CAP 192

__global__ __launch_bounds__(RB_T) void radius_kernel(const float* __restrict__ pos)
{
    __shared__ float scx[RB_C], scy[RB_C], scz[RB_C];
    __shared__ int   scnt[RB_C];
    __shared__ int   sidx[RB_C][RB_CAP];
    __shared__ float sd2[RB_C][RB_CAP];

    int t = threadIdx.x;
    int c0 = blockIdx.x * RB_C;
    if (t < RB_C) {
        scx[t] = g_pos_s[3 * (c0 + t) + 0];
        scy[t] = g_pos_s[3 * (c0 + t) + 1];
        scz[t] = g_pos_s[3 * (c0 + t) + 2];
        scnt[t] = 0;
    }
    __syncthreads();

    for (int j = t; j < NP; j += RB_T) {
        float x = pos[3 * j + 0], y = pos[3 * j + 1], z = pos[3 * j + 2];
#pragma unroll
        for (int c = 0; c < RB_C; c++) {
            float dx = __fadd_rn(scx[c], -x);
            float dy = __fadd_rn(scy[c], -y);
            float dz = __fadd_rn(scz[c], -z);
            float d2 = __fmaf_rn(dz, dz, __fmaf_rn(dy, dy, __fmul_rn(dx, dx)));
            if (d2 <= R2F) {
                int n = atomicAdd(&scnt[c], 1);
                if (n < RB_CAP) { sidx[c][n] = j; sd2[c][n] = d2; }
            }
        }
    }
    __syncthreads();

    for (int c = 0; c < RB_C; c++) {
        int cnt = min(scnt[c], RB_CAP);
        int cg = c0 + c;
        if (cnt <= KN) {
            if (t < cnt) g_nbr[cg * KN + t] = sidx[c][t];
            if (t == 0)  g_cnt[cg] = cnt;
        } else {
            for (int i = t; i < cnt; i += RB_T) {
                float di = sd2[c][i]; int ii = sidx[c][i];
                int rank = 0;
                for (int jj = 0; jj < cnt; jj++) {
                    float dj = sd2[c][jj];
                    rank += (dj < di) || (dj == di && sidx[c][jj] < ii);
                }
                if (rank < KN) g_nbr[cg * KN + rank] = ii;
            }
            if (t == 0) g_cnt[cg] = KN;
        }
    }
}

// ---------------------------------------------------------------------------
// 4) Per-edge MLP + max-pool (unchanged, passing).
// ---------------------------------------------------------------------------
#define ML_T    256
#define ML_GRID 304

#define OFF_W1 0
#define OFF_W2 (OFF_W1 + FD * FH)
#define OFF_W3 (OFF_W2 + FH * FH)
#define OFF_B1 (OFF_W3 + FH * FO)
#define OFF_B2 (OFF_B1 + FH)
#define OFF_B3 (OFF_B2 + FH)
#define OFF_F  (OFF_B3 + FO)
#define OFF_H  (OFF_F + KN * FPAD)
#define OFF_O  (OFF_H + KN * FPAD)
#define ML_SMEM ((OFF_O + FO) * 4)

__global__ __launch_bounds__(ML_T, 2) void mlp_kernel(
    const float* __restrict__ x, const float* __restrict__ pos,
    const float* __restrict__ W1, const float* __restrict__ b1,
    const float* __restrict__ W2, const float* __restrict__ b2,
    const float* __restrict__ W3, const float* __restrict__ b3,
    float* __restrict__ out)
{
    extern __shared__ float sm[];
    float* sW1 = sm + OFF_W1;
    float* sW2 = sm + OFF_W2;
    float* sW3 = sm + OFF_W3;
    float* sb1 = sm + OFF_B1;
    float* sb2 = sm + OFF_B2;
    float* sb3 = sm + OFF_B3;
    float* sF  = sm + OFF_F;
    float* sH  = sm + OFF_H;
    int*   sO  = (int*)(sm + OFF_O);

    int t = threadIdx.x;
    for (int i = t; i < FD * FH; i += ML_T) sW1[i] = W1[i];
    for (int i = t; i < FH * FH; i += ML_T) sW2[i] = W2[i];
    for (int i = t; i < FH * FO; i += ML_T) sW3[i] = W3[i];
    if (t < FH) { sb1[t] = b1[t]; sb2[t] = b2[t]; }
    if (t < FO) sb3[t] = b3[t];

    int ei = t >> 4, ci = t & 15;

    for (int c = blockIdx.x; c < MC; c += gridDim.x) {
        __syncthreads();
        if (t < FO) sO[t] = 0;
        int E = g_cnt[c];
        float cx = g_pos_s[3 * c + 0], cy = g_pos_s[3 * c + 1], cz = g_pos_s[3 * c + 2];

        {
            int e = t >> 2, q = t & 3;
            if (e < E) {
                int nb = g_nbr[c * KN + e];
                const float4* xr = (const float4*)(x + (size_t)nb * FIN);
                float4* dst = (float4*)(sF + e * FPAD + q * 16);
                dst[0] = xr[q * 4 + 0]; dst[1] = xr[q * 4 + 1];
                dst[2] = xr[q * 4 + 2]; dst[3] = xr[q * 4 + 3];
                if (q == 0) {
                    sF[e * FPAD + 64] = pos[3 * nb + 0] - cx;
                    sF[e * FPAD + 65] = pos[3 * nb + 1] - cy;
                    sF[e * FPAD + 66] = pos[3 * nb + 2] - cz;
                    sF[e * FPAD + 67] = 0.0f;
                }
            }
        }
        __syncthreads();
        int ET = (E + 3) >> 2;

        if (ei < ET) {
            float acc[4][4];
#pragma unroll
            for (int j = 0; j < 4; j++)
#pragma unroll
                for (int a = 0; a < 4; a++) acc[j][a] = sb1[ci * 4 + a];
#pragma unroll 4
            for (int k = 0; k < FD; k++) {
                float4 wv = *(const float4*)(sW1 + k * FH + ci * 4);
                float f[4];
#pragma unroll
                for (int j = 0; j < 4; j++) f[j] = sF[(4 * ei + j) * FPAD + k];
#pragma unroll
                for (int j = 0; j < 4; j++) {
                    acc[j][0] += f[j] * wv.x; acc[j][1] += f[j] * wv.y;
                    acc[j][2] += f[j] * wv.z; acc[j][3] += f[j] * wv.w;
                }
            }
#pragma unroll
            for (int j = 0; j < 4; j++)
#pragma unroll
                for (int a = 0; a < 4; a++)
                    sH[(4 * ei + j) * FPAD + ci * 4 + a] = fmaxf(acc[j][a], 0.0f);
        }
        __syncthreads();

        if (ei < ET) {
            float acc[4][4];
#pragma unroll
            for (int j = 0; j < 4; j++)
#pragma unroll
                for (int a = 0; a < 4; a++) acc[j][a] = sb2[ci * 4 + a];
#pragma unroll 4
            for (int k = 0; k < FH; k++) {
                float4 wv = *(const float4*)(sW2 + k * FH + ci * 4);
                float f[4];
#pragma unroll
                for (int j = 0; j < 4; j++) f[j] = sH[(4 * ei + j) * FPAD + k];
#pragma unroll
                for (int j = 0; j < 4; j++) {
                    acc[j][0] += f[j] * wv.x; acc[j][1] += f[j] * wv.y;
                    acc[j][2] += f[j] * wv.z; acc[j][3] += f[j] * wv.w;
                }
            }
#pragma unroll
            for (int j = 0; j < 4; j++)
#pragma unroll
                for (int a = 0; a < 4; a++)
                    sF[(4 * ei + j) * FPAD + ci * 4 + a] = fmaxf(acc[j][a], 0.0f);
        }
        __syncthreads();

        if (ei < ET) {
            float acc[4][8];
#pragma unroll
            for (int j = 0; j < 4; j++)
#pragma unroll
                for (int a = 0; a < 8; a++) acc[j][a] = sb3[ci * 8 + a];
#pragma unroll 4
            for (int k = 0; k < FH; k++) {
                float4 wa = *(const float4*)(sW3 + k * FO + ci * 8);
                float4 wb = *(const float4*)(sW3 + k * FO + ci * 8 + 4);
                float f[4];
#pragma unroll
                for (int j = 0; j < 4; j++) f[j] = sF[(4 * ei + j) * FPAD + k];
#pragma unroll
                for (int j = 0; j < 4; j++) {
                    acc[j][0] += f[j] * wa.x; acc[j][1] += f[j] * wa.y;
                    acc[j][2] += f[j] * wa.z; acc[j][3] += f[j] * wa.w;
                    acc[j][4] += f[j] * wb.x; acc[j][5] += f[j] * wb.y;
                    acc[j][6] += f[j] * wb.z; acc[j][7] += f[j] * wb.w;
                }
            }
#pragma unroll
            for (int a = 0; a < 8; a++) {
                float mv = -1.0f;
#pragma unroll
                for (int j = 0; j < 4; j++)
                    if (4 * ei + j < E) mv = fmaxf(mv, fmaxf(acc[j][a], 0.0f));
                if (mv >= 0.0f) atomicMax(&sO[ci * 8 + a], __float_as_int(mv));
            }
        }
        __syncthreads();
        if (t < FO) out[(size_t)c * FO + t] = __int_as_float(sO[t]);
    }
}

// ---------------------------------------------------------------------------
extern "C" void kernel_launch(void* const* d_in, const int* in_sizes, int n_in,
                              void* d_out, int out_size)
{
    const float* x   = (const float*)d_in[0];
    const float* pos = (const float*)d_in[1];
    const float* W1 = (const float*)d_in[3];
    const float* b1 = (const float*)d_in[4];
    const float* W2 = (const float*)d_in[5];
    const float* b2 = (const float*)d_in[6];
    const float* W3 = (const float*)d_in[7];
    const float* b3 = (const float*)d_in[8];
    float* out = (float*)d_out;

    cudaFuncSetAttribute(build_kernel, cudaFuncAttributeMaxDynamicSharedMemorySize, BLD_SMEM);
    cudaFuncSetAttribute(fps_kernel,   cudaFuncAttributeMaxDynamicSharedMemorySize, FPS_SMEM);
    cudaFuncSetAttribute(mlp_kernel,   cudaFuncAttributeMaxDynamicSharedMemorySize, ML_SMEM);

    build_kernel<<<1, BLD_T, BLD_SMEM>>>(pos);
    fps_kernel<<<1, FPS_T, FPS_SMEM>>>(pos);
    gather_kernel<<<(MC + 255) / 256, 256>>>(pos, out, out_size);
    radius_kernel<<<MC / RB_C, RB_T>>>(pos);
    mlp_kernel<<<ML_GRID, ML_T, ML_SMEM>>>(x, pos, W1, b1, W2, b2, W3, b3, out);
}